// round 1
// baseline (speedup 1.0000x reference)
#include <cuda_runtime.h>
#include <cuda_bf16.h>

// Problem constants (validated against in_sizes at launch where cheap)
#define MAX_I   100000
#define MAX_B   16384
#define NUM_SEG (MAX_B * 5)

// Scratch (no allocation allowed)
__device__ float g_rowsum[MAX_I];
__device__ float g_segsum[NUM_SEG];
__device__ float g_segcnt[NUM_SEG];

// ---------------------------------------------------------------------------
// Kernel 0: zero the segment accumulators (d_out-independent, every call)
// ---------------------------------------------------------------------------
__global__ void zero_seg_kernel(int n) {
    int i = blockIdx.x * blockDim.x + threadIdx.x;
    if (i < n) {
        g_segsum[i] = 0.0f;
        g_segcnt[i] = 0.0f;
    }
}

// ---------------------------------------------------------------------------
// Kernel 1: rowsum[i] = sum_d Mr[i, d]   (one warp per row, coalesced 256B)
// ---------------------------------------------------------------------------
__global__ void rowsum_kernel(const float* __restrict__ Mr,
                              int num_items) {
    int warp = (blockIdx.x * blockDim.x + threadIdx.x) >> 5;
    int lane = threadIdx.x & 31;
    if (warp >= num_items) return;
    const float2* row = reinterpret_cast<const float2*>(Mr + (long)warp * 64);
    float2 v = row[lane];
    float s = v.x + v.y;
    #pragma unroll
    for (int o = 16; o; o >>= 1) s += __shfl_down_sync(0xFFFFFFFFu, s, o);
    if (lane == 0) g_rowsum[warp] = s;
}

// ---------------------------------------------------------------------------
// Kernel 2: segmented accumulation over sorted seg_ids.
// Each thread owns a contiguous CHUNK; run-length accumulate, flush with
// atomicAdd only on segment change / chunk boundary.
// ---------------------------------------------------------------------------
#define CHUNK 64

__global__ void seg_accum_kernel(const int* __restrict__ flat_items,
                                 const int* __restrict__ seg_ids,
                                 const int* __restrict__ item_idx,
                                 int T) {
    long base = (long)(blockIdx.x * blockDim.x + threadIdx.x) * CHUNK;
    if (base >= T) return;
    int n = (int)min((long)CHUNK, (long)T - base);

    int   cur = -1;
    float acc_s = 0.0f;
    float acc_c = 0.0f;

    const int4* sg4 = reinterpret_cast<const int4*>(seg_ids + base);
    const int4* fi4 = reinterpret_cast<const int4*>(flat_items + base);

    // T is a multiple of 16 in this problem; fall back to scalar tail anyway.
    int nv = n >> 2;
    for (int v = 0; v < nv; v++) {
        int4 sg = sg4[v];
        int4 fi = fi4[v];
        #pragma unroll
        for (int k = 0; k < 4; k++) {
            int seg = (k == 0) ? sg.x : (k == 1) ? sg.y : (k == 2) ? sg.z : sg.w;
            int it  = (k == 0) ? fi.x : (k == 1) ? fi.y : (k == 2) ? fi.z : fi.w;
            if (seg != cur) {
                if (cur >= 0) {
                    atomicAdd(&g_segsum[cur], acc_s);
                    atomicAdd(&g_segcnt[cur], acc_c);
                }
                cur = seg; acc_s = 0.0f; acc_c = 0.0f;
            }
            // segment -> sample index = seg / 5 (R = 5)
            int tgt = item_idx[seg / 5];
            if (it != tgt) {
                acc_s += g_rowsum[it];
                acc_c += 1.0f;
            }
        }
    }
    for (int t = (nv << 2); t < n; t++) {
        int seg = seg_ids[base + t];
        int it  = flat_items[base + t];
        if (seg != cur) {
            if (cur >= 0) {
                atomicAdd(&g_segsum[cur], acc_s);
                atomicAdd(&g_segcnt[cur], acc_c);
            }
            cur = seg; acc_s = 0.0f; acc_c = 0.0f;
        }
        int tgt = item_idx[seg / 5];
        if (it != tgt) {
            acc_s += g_rowsum[it];
            acc_c += 1.0f;
        }
    }
    if (cur >= 0) {
        atomicAdd(&g_segsum[cur], acc_s);
        atomicAdd(&g_segcnt[cur], acc_c);
    }
}

// ---------------------------------------------------------------------------
// Kernel 3: finalize. One warp per sample.
// rui = dot(ue,ie) + uu_mpc * sum(ie) + ub + ib + avg; clip [1,5]
// ---------------------------------------------------------------------------
__global__ void finalize_kernel(const int* __restrict__ user_idx,
                                const int* __restrict__ item_idx,
                                const float* __restrict__ user_emb,
                                const float* __restrict__ item_emb,
                                const float* __restrict__ user_bias,
                                const float* __restrict__ item_bias,
                                const float* __restrict__ global_avg,
                                float* __restrict__ out,
                                int Bn) {
    int warp = (blockIdx.x * blockDim.x + threadIdx.x) >> 5;
    int lane = threadIdx.x & 31;
    if (warp >= Bn) return;

    int u = user_idx[warp];
    int i = item_idx[warp];

    const float2* ue = reinterpret_cast<const float2*>(user_emb + (long)u * 64);
    const float2* ie = reinterpret_cast<const float2*>(item_emb + (long)i * 64);
    float2 a = ue[lane];
    float2 b = ie[lane];
    float dot  = a.x * b.x + a.y * b.y;
    float isum = b.x + b.y;
    #pragma unroll
    for (int o = 16; o; o >>= 1) {
        dot  += __shfl_down_sync(0xFFFFFFFFu, dot,  o);
        isum += __shfl_down_sync(0xFFFFFFFFu, isum, o);
    }

    if (lane == 0) {
        float uu = 0.0f;
        #pragma unroll
        for (int r = 0; r < 5; r++) {
            float c = g_segcnt[warp * 5 + r];
            float s = g_segsum[warp * 5 + r];
            if (c > 0.0f) uu += s * rsqrtf(fmaxf(c, 1.0f));
        }
        float rui = dot + uu * isum + user_bias[u] + item_bias[i] + global_avg[0];
        rui = fminf(fmaxf(rui, 1.0f), 5.0f);
        out[warp] = rui;
    }
}

// ---------------------------------------------------------------------------
// Launch
// ---------------------------------------------------------------------------
extern "C" void kernel_launch(void* const* d_in, const int* in_sizes, int n_in,
                              void* d_out, int out_size) {
    const int*   user_idx   = (const int*)  d_in[0];
    const int*   item_idx   = (const int*)  d_in[1];
    const int*   flat_items = (const int*)  d_in[2];
    const int*   seg_ids    = (const int*)  d_in[3];
    const float* user_emb   = (const float*)d_in[4];
    const float* item_emb   = (const float*)d_in[5];
    const float* Mr         = (const float*)d_in[6];
    const float* user_bias  = (const float*)d_in[7];
    const float* item_bias  = (const float*)d_in[8];
    const float* global_avg = (const float*)d_in[9];
    float* out = (float*)d_out;

    const int Bn = in_sizes[0];            // 16384
    const int T  = in_sizes[2];            // 1,638,400
    const int I  = in_sizes[6] / 64;       // 100000 (Mr rows)
    const int num_seg = Bn * 5;

    // 0) zero segment accumulators
    {
        int threads = 256;
        int blocks = (num_seg + threads - 1) / threads;
        zero_seg_kernel<<<blocks, threads>>>(num_seg);
    }
    // 1) per-item row sums (warp per row)
    {
        int threads = 256;                 // 8 warps/block
        int blocks = (I + 7) / 8;
        rowsum_kernel<<<blocks, threads>>>(Mr, I);
    }
    // 2) segmented accumulation
    {
        int nthreads_total = (T + CHUNK - 1) / CHUNK;  // 25600
        int threads = 256;
        int blocks = (nthreads_total + threads - 1) / threads;
        seg_accum_kernel<<<blocks, threads>>>(flat_items, seg_ids, item_idx, T);
    }
    // 3) finalize (warp per sample)
    {
        int threads = 256;                 // 8 warps/block
        int blocks = (Bn + 7) / 8;
        finalize_kernel<<<blocks, threads>>>(user_idx, item_idx, user_emb, item_emb,
                                             user_bias, item_bias, global_avg,
                                             out, Bn);
    }
}

// round 2
// speedup vs baseline: 1.8011x; 1.8011x over previous
#include <cuda_runtime.h>
#include <cuda_bf16.h>

#define MAX_I   100000
#define MAX_B   16384
#define NUM_SEG (MAX_B * 5)

__device__ float g_rowsum[MAX_I];
__device__ float g_segsum[NUM_SEG];
__device__ float g_segcnt[NUM_SEG];

// ---------------------------------------------------------------------------
// Kernel 1 (fused): zero segment accumulators + rowsum[i] = sum_d Mr[i,d]
// One warp per Mr row; first NUM_SEG threads also zero the accumulators.
// ---------------------------------------------------------------------------
__global__ void rowsum_zero_kernel(const float* __restrict__ Mr,
                                   int num_items) {
    int tid  = blockIdx.x * blockDim.x + threadIdx.x;
    if (tid < NUM_SEG) {
        g_segsum[tid] = 0.0f;
        g_segcnt[tid] = 0.0f;
    }
    int warp = tid >> 5;
    int lane = threadIdx.x & 31;
    if (warp >= num_items) return;
    const float2* row = reinterpret_cast<const float2*>(Mr + (long)warp * 64);
    float2 v = row[lane];
    float s = v.x + v.y;
    #pragma unroll
    for (int o = 16; o; o >>= 1) s += __shfl_down_sync(0xFFFFFFFFu, s, o);
    if (lane == 0) g_rowsum[warp] = s;
}

// ---------------------------------------------------------------------------
// Kernel 2: segmented accumulation over sorted seg_ids.
// CHUNK=16 per thread (4x int4), run-length accumulate, flush on boundary.
// ---------------------------------------------------------------------------
#define CHUNK 16

__global__ void seg_accum_kernel(const int* __restrict__ flat_items,
                                 const int* __restrict__ seg_ids,
                                 const int* __restrict__ item_idx,
                                 int T) {
    long base = (long)(blockIdx.x * blockDim.x + threadIdx.x) * CHUNK;
    if (base >= T) return;

    const int4* sg4 = reinterpret_cast<const int4*>(seg_ids + base);
    const int4* fi4 = reinterpret_cast<const int4*>(flat_items + base);

    int   cur   = -1;
    int   tgt   = -1;
    float acc_s = 0.0f;
    float acc_c = 0.0f;

    if (base + CHUNK <= T) {
        // Full vectorized chunk: preload all 8 int4s for max MLP.
        int4 sg[4], fi[4];
        #pragma unroll
        for (int v = 0; v < 4; v++) { sg[v] = sg4[v]; fi[v] = fi4[v]; }
        #pragma unroll
        for (int v = 0; v < 4; v++) {
            #pragma unroll
            for (int k = 0; k < 4; k++) {
                int seg = (k == 0) ? sg[v].x : (k == 1) ? sg[v].y : (k == 2) ? sg[v].z : sg[v].w;
                int it  = (k == 0) ? fi[v].x : (k == 1) ? fi[v].y : (k == 2) ? fi[v].z : fi[v].w;
                if (seg != cur) {
                    if (cur >= 0) {
                        atomicAdd(&g_segsum[cur], acc_s);
                        atomicAdd(&g_segcnt[cur], acc_c);
                    }
                    cur = seg; acc_s = 0.0f; acc_c = 0.0f;
                    tgt = item_idx[seg / 5];
                }
                if (it != tgt) {
                    acc_s += g_rowsum[it];
                    acc_c += 1.0f;
                }
            }
        }
    } else {
        int n = (int)((long)T - base);
        for (int t = 0; t < n; t++) {
            int seg = seg_ids[base + t];
            int it  = flat_items[base + t];
            if (seg != cur) {
                if (cur >= 0) {
                    atomicAdd(&g_segsum[cur], acc_s);
                    atomicAdd(&g_segcnt[cur], acc_c);
                }
                cur = seg; acc_s = 0.0f; acc_c = 0.0f;
                tgt = item_idx[seg / 5];
            }
            if (it != tgt) {
                acc_s += g_rowsum[it];
                acc_c += 1.0f;
            }
        }
    }
    if (cur >= 0) {
        atomicAdd(&g_segsum[cur], acc_s);
        atomicAdd(&g_segcnt[cur], acc_c);
    }
}

// ---------------------------------------------------------------------------
// Kernel 3: finalize. 8-lane group per sample, 4 samples per warp.
// rui = dot(ue,ie) + uu_mpc * sum(ie) + ub + ib + avg; clip [1,5]
// Each lane loads 2x float4 per row (8 lanes * 2 * 16B = 256B = full row).
// ---------------------------------------------------------------------------
__global__ void finalize_kernel(const int* __restrict__ user_idx,
                                const int* __restrict__ item_idx,
                                const float* __restrict__ user_emb,
                                const float* __restrict__ item_emb,
                                const float* __restrict__ user_bias,
                                const float* __restrict__ item_bias,
                                const float* __restrict__ global_avg,
                                float* __restrict__ out,
                                int Bn) {
    int tid    = blockIdx.x * blockDim.x + threadIdx.x;
    int sample = tid >> 3;           // 8 lanes per sample
    int sub    = tid & 7;
    if (sample >= Bn) return;

    int u = user_idx[sample];
    int i = item_idx[sample];

    const float4* ue = reinterpret_cast<const float4*>(user_emb + (long)u * 64);
    const float4* ie = reinterpret_cast<const float4*>(item_emb + (long)i * 64);

    // 4 independent 16B loads in flight per lane
    float4 a0 = ue[sub];
    float4 a1 = ue[sub + 8];
    float4 b0 = ie[sub];
    float4 b1 = ie[sub + 8];

    float dot  = a0.x*b0.x + a0.y*b0.y + a0.z*b0.z + a0.w*b0.w
               + a1.x*b1.x + a1.y*b1.y + a1.z*b1.z + a1.w*b1.w;
    float isum = b0.x + b0.y + b0.z + b0.w + b1.x + b1.y + b1.z + b1.w;

    #pragma unroll
    for (int o = 4; o; o >>= 1) {
        dot  += __shfl_xor_sync(0xFFFFFFFFu, dot,  o);
        isum += __shfl_xor_sync(0xFFFFFFFFu, isum, o);
    }

    if (sub == 0) {
        float uu = 0.0f;
        #pragma unroll
        for (int r = 0; r < 5; r++) {
            float c = g_segcnt[sample * 5 + r];
            float s = g_segsum[sample * 5 + r];
            if (c > 0.0f) uu += s * rsqrtf(fmaxf(c, 1.0f));
        }
        float rui = dot + uu * isum + user_bias[u] + item_bias[i] + global_avg[0];
        rui = fminf(fmaxf(rui, 1.0f), 5.0f);
        out[sample] = rui;
    }
}

// ---------------------------------------------------------------------------
// Launch
// ---------------------------------------------------------------------------
extern "C" void kernel_launch(void* const* d_in, const int* in_sizes, int n_in,
                              void* d_out, int out_size) {
    const int*   user_idx   = (const int*)  d_in[0];
    const int*   item_idx   = (const int*)  d_in[1];
    const int*   flat_items = (const int*)  d_in[2];
    const int*   seg_ids    = (const int*)  d_in[3];
    const float* user_emb   = (const float*)d_in[4];
    const float* item_emb   = (const float*)d_in[5];
    const float* Mr         = (const float*)d_in[6];
    const float* user_bias  = (const float*)d_in[7];
    const float* item_bias  = (const float*)d_in[8];
    const float* global_avg = (const float*)d_in[9];
    float* out = (float*)d_out;

    const int Bn = in_sizes[0];            // 16384
    const int T  = in_sizes[2];            // 1,638,400
    const int I  = in_sizes[6] / 64;       // 100000

    // 1) zero accumulators + per-item row sums (fused)
    {
        int threads = 256;                 // 8 warps/block
        int blocks = (I + 7) / 8;          // one warp per row
        rowsum_zero_kernel<<<blocks, threads>>>(Mr, I);
    }
    // 2) segmented accumulation
    {
        int nthreads_total = (T + CHUNK - 1) / CHUNK;   // 102400
        int threads = 256;
        int blocks = (nthreads_total + threads - 1) / threads;
        seg_accum_kernel<<<blocks, threads>>>(flat_items, seg_ids, item_idx, T);
    }
    // 3) finalize (8-lane group per sample)
    {
        int threads = 256;                 // 32 samples/block
        int blocks = (Bn * 8 + threads - 1) / threads;
        finalize_kernel<<<blocks, threads>>>(user_idx, item_idx, user_emb, item_emb,
                                             user_bias, item_bias, global_avg,
                                             out, Bn);
    }
}

// round 3
// speedup vs baseline: 2.1476x; 1.1924x over previous
#include <cuda_runtime.h>
#include <cuda_bf16.h>

#define MAX_I   100000
#define MAX_B   16384
#define NUM_SEG (MAX_B * 5)

__device__ float g_rowsum[MAX_I];
__device__ float g_segsum[NUM_SEG];
__device__ float g_segcnt[NUM_SEG];

// ---------------------------------------------------------------------------
// Kernel 1 (fused): zero segment accumulators + rowsum[i] = sum_d Mr[i,d]
// 8 rows per warp: 4 coalesced float4 loads/thread (MLP=4), then 4 parallel
// half-warp shuffle reductions. flat f4 index = j*32+lane -> row j*2+(lane>>4),
// within-row pos = lane&15.
// ---------------------------------------------------------------------------
__global__ void rowsum_zero_kernel(const float* __restrict__ Mr,
                                   int num_items) {
    int tid  = blockIdx.x * blockDim.x + threadIdx.x;
    if (tid < NUM_SEG) {
        g_segsum[tid] = 0.0f;
        g_segcnt[tid] = 0.0f;
    }
    int warp = tid >> 5;
    int lane = threadIdx.x & 31;
    int row0 = warp * 8;
    if (row0 >= num_items) return;

    const float4* base = reinterpret_cast<const float4*>(Mr) + (long)row0 * 16;

    float s[4];
    if (row0 + 8 <= num_items) {
        #pragma unroll
        for (int j = 0; j < 4; j++) {
            float4 v = base[j * 32 + lane];
            s[j] = (v.x + v.y) + (v.z + v.w);
        }
    } else {
        #pragma unroll
        for (int j = 0; j < 4; j++) {
            int f = j * 32 + lane;
            int r = row0 + (f >> 4);
            if (r < num_items) {
                float4 v = base[f];
                s[j] = (v.x + v.y) + (v.z + v.w);
            } else {
                s[j] = 0.0f;
            }
        }
    }

    // reduce over the 16 lanes sharing the same half (bits 0..3)
    #pragma unroll
    for (int o = 8; o; o >>= 1) {
        #pragma unroll
        for (int j = 0; j < 4; j++)
            s[j] += __shfl_xor_sync(0xFFFFFFFFu, s[j], o);
    }

    if ((lane & 15) == 0) {
        int rbase = row0 + (lane >> 4);
        #pragma unroll
        for (int j = 0; j < 4; j++) {
            int r = rbase + j * 2;
            if (r < num_items) g_rowsum[r] = s[j];
        }
    }
}

// ---------------------------------------------------------------------------
// Kernel 2: segmented accumulation over sorted seg_ids.
// CHUNK=16 per thread (4x int4), run-length accumulate, flush on boundary.
// ---------------------------------------------------------------------------
#define CHUNK 16

__global__ void seg_accum_kernel(const int* __restrict__ flat_items,
                                 const int* __restrict__ seg_ids,
                                 const int* __restrict__ item_idx,
                                 int T) {
    long base = (long)(blockIdx.x * blockDim.x + threadIdx.x) * CHUNK;
    if (base >= T) return;

    const int4* sg4 = reinterpret_cast<const int4*>(seg_ids + base);
    const int4* fi4 = reinterpret_cast<const int4*>(flat_items + base);

    int   cur   = -1;
    int   tgt   = -1;
    float acc_s = 0.0f;
    float acc_c = 0.0f;

    if (base + CHUNK <= T) {
        int4 sg[4], fi[4];
        #pragma unroll
        for (int v = 0; v < 4; v++) { sg[v] = sg4[v]; fi[v] = fi4[v]; }
        #pragma unroll
        for (int v = 0; v < 4; v++) {
            #pragma unroll
            for (int k = 0; k < 4; k++) {
                int seg = (k == 0) ? sg[v].x : (k == 1) ? sg[v].y : (k == 2) ? sg[v].z : sg[v].w;
                int it  = (k == 0) ? fi[v].x : (k == 1) ? fi[v].y : (k == 2) ? fi[v].z : fi[v].w;
                if (seg != cur) {
                    if (cur >= 0) {
                        atomicAdd(&g_segsum[cur], acc_s);
                        atomicAdd(&g_segcnt[cur], acc_c);
                    }
                    cur = seg; acc_s = 0.0f; acc_c = 0.0f;
                    tgt = item_idx[seg / 5];
                }
                if (it != tgt) {
                    acc_s += g_rowsum[it];
                    acc_c += 1.0f;
                }
            }
        }
    } else {
        int n = (int)((long)T - base);
        for (int t = 0; t < n; t++) {
            int seg = seg_ids[base + t];
            int it  = flat_items[base + t];
            if (seg != cur) {
                if (cur >= 0) {
                    atomicAdd(&g_segsum[cur], acc_s);
                    atomicAdd(&g_segcnt[cur], acc_c);
                }
                cur = seg; acc_s = 0.0f; acc_c = 0.0f;
                tgt = item_idx[seg / 5];
            }
            if (it != tgt) {
                acc_s += g_rowsum[it];
                acc_c += 1.0f;
            }
        }
    }
    if (cur >= 0) {
        atomicAdd(&g_segsum[cur], acc_s);
        atomicAdd(&g_segcnt[cur], acc_c);
    }
}

// ---------------------------------------------------------------------------
// Kernel 3: finalize. 8-lane group per sample, 4 samples per warp.
// rui = dot(ue,ie) + uu_mpc * sum(ie) + ub + ib + avg; clip [1,5]
// ---------------------------------------------------------------------------
__global__ void finalize_kernel(const int* __restrict__ user_idx,
                                const int* __restrict__ item_idx,
                                const float* __restrict__ user_emb,
                                const float* __restrict__ item_emb,
                                const float* __restrict__ user_bias,
                                const float* __restrict__ item_bias,
                                const float* __restrict__ global_avg,
                                float* __restrict__ out,
                                int Bn) {
    int tid    = blockIdx.x * blockDim.x + threadIdx.x;
    int sample = tid >> 3;           // 8 lanes per sample
    int sub    = tid & 7;
    if (sample >= Bn) return;

    int u = user_idx[sample];
    int i = item_idx[sample];

    const float4* ue = reinterpret_cast<const float4*>(user_emb + (long)u * 64);
    const float4* ie = reinterpret_cast<const float4*>(item_emb + (long)i * 64);

    float4 a0 = ue[sub];
    float4 a1 = ue[sub + 8];
    float4 b0 = ie[sub];
    float4 b1 = ie[sub + 8];

    float dot  = a0.x*b0.x + a0.y*b0.y + a0.z*b0.z + a0.w*b0.w
               + a1.x*b1.x + a1.y*b1.y + a1.z*b1.z + a1.w*b1.w;
    float isum = b0.x + b0.y + b0.z + b0.w + b1.x + b1.y + b1.z + b1.w;

    #pragma unroll
    for (int o = 4; o; o >>= 1) {
        dot  += __shfl_xor_sync(0xFFFFFFFFu, dot,  o);
        isum += __shfl_xor_sync(0xFFFFFFFFu, isum, o);
    }

    if (sub == 0) {
        float uu = 0.0f;
        #pragma unroll
        for (int r = 0; r < 5; r++) {
            float c = g_segcnt[sample * 5 + r];
            float s = g_segsum[sample * 5 + r];
            if (c > 0.0f) uu += s * rsqrtf(fmaxf(c, 1.0f));
        }
        float rui = dot + uu * isum + user_bias[u] + item_bias[i] + global_avg[0];
        rui = fminf(fmaxf(rui, 1.0f), 5.0f);
        out[sample] = rui;
    }
}

// ---------------------------------------------------------------------------
// Launch
// ---------------------------------------------------------------------------
extern "C" void kernel_launch(void* const* d_in, const int* in_sizes, int n_in,
                              void* d_out, int out_size) {
    const int*   user_idx   = (const int*)  d_in[0];
    const int*   item_idx   = (const int*)  d_in[1];
    const int*   flat_items = (const int*)  d_in[2];
    const int*   seg_ids    = (const int*)  d_in[3];
    const float* user_emb   = (const float*)d_in[4];
    const float* item_emb   = (const float*)d_in[5];
    const float* Mr         = (const float*)d_in[6];
    const float* user_bias  = (const float*)d_in[7];
    const float* item_bias  = (const float*)d_in[8];
    const float* global_avg = (const float*)d_in[9];
    float* out = (float*)d_out;

    const int Bn = in_sizes[0];            // 16384
    const int T  = in_sizes[2];            // 1,638,400
    const int I  = in_sizes[6] / 64;       // 100000

    // 1) zero accumulators + per-item row sums (8 rows/warp)
    {
        int warps = (I + 7) / 8;                       // 12500
        int threads_total = warps * 32;                // 400000 (covers NUM_SEG zeroing)
        int threads = 256;
        int blocks = (threads_total + threads - 1) / threads;
        rowsum_zero_kernel<<<blocks, threads>>>(Mr, I);
    }
    // 2) segmented accumulation
    {
        int nthreads_total = (T + CHUNK - 1) / CHUNK;   // 102400
        int threads = 256;
        int blocks = (nthreads_total + threads - 1) / threads;
        seg_accum_kernel<<<blocks, threads>>>(flat_items, seg_ids, item_idx, T);
    }
    // 3) finalize (8-lane group per sample)
    {
        int threads = 256;                 // 32 samples/block
        int blocks = (Bn * 8 + threads - 1) / threads;
        finalize_kernel<<<blocks, threads>>>(user_idx, item_idx, user_emb, item_emb,
                                             user_bias, item_bias, global_avg,
                                             out, Bn);
    }
}